// round 6
// baseline (speedup 1.0000x reference)
#include <cuda_runtime.h>

// Scalar accumulator + completion counter (device globals; self-resetting so
// the kernel is deterministic across CUDA-graph replays).
__device__ double       g_acc  = 0.0;
__device__ unsigned int g_done = 0u;

// Per-row work, all fp32. Accumulates:
//   lg2  += log2(sum exp(l))          (CE log-sum-exp part, ln2 folded later)
//   lt   += l[target]                 (CE picked-logit part)
//   ssq  += (0.5 - p0)^2              (r2 squared deviation)
//   nhet += (target == 1)
// No max-subtraction: logits ~ N(0,1) (|l| < ~6), exp cannot overflow.
__device__ __forceinline__ void row(float l0, float l1, float l2, int t,
                                    float& lg2, float& lt,
                                    float& ssq, int& nhet) {
    float e0 = __expf(l0);
    float e1 = __expf(l1);
    float e2 = __expf(l2);
    float s  = e0 + e1 + e2;
    lg2 += __log2f(s);
    float p0 = __fdividef(e0, s);
    float d  = 0.5f - p0;
    ssq  = fmaf(d, d, ssq);
    lt  += (t == 1) ? l1 : ((t == 2) ? l2 : l0);
    nhet += (t == 1) ? 1 : 0;
}

// One group of 4 rows. Group r2 contribution: cnt cancels out of the
// reference formula, leaving exactly 4 * nhet * ssq (to be subtracted).
__device__ __forceinline__ void group4(const float4* __restrict__ lg,
                                       const int4*  __restrict__ tg, int g,
                                       float& lg2, float& lt, float& r2acc) {
    float4 a = lg[g * 3 + 0];
    float4 b = lg[g * 3 + 1];
    float4 c = lg[g * 3 + 2];
    int4   t = tg[g];
    float ssq = 0.0f;
    int nhet = 0;
    row(a.x, a.y, a.z, t.x, lg2, lt, ssq, nhet);
    row(a.w, b.x, b.y, t.y, lg2, lt, ssq, nhet);
    row(b.z, b.w, c.x, t.z, lg2, lt, ssq, nhet);
    row(c.y, c.z, c.w, t.w, lg2, lt, ssq, nhet);
    r2acc = fmaf((float)(4 * nhet), ssq, r2acc);
}

__global__ void __launch_bounds__(256)
imputation_loss_kernel(const float4* __restrict__ lg,
                       const int4*  __restrict__ tg,
                       int nunits,          // units of 2 groups (8 rows)
                       const float* __restrict__ logits_rest,
                       const int*   __restrict__ targets_rest,
                       int rest_rows,       // rows beyond nunits*8
                       float* __restrict__ out) {
    float lg2 = 0.0f, lt = 0.0f, r2acc = 0.0f;

    const int stride = gridDim.x * blockDim.x;
    for (int u = blockIdx.x * blockDim.x + threadIdx.x; u < nunits; u += stride) {
        group4(lg, tg, 2 * u,     lg2, lt, r2acc);
        group4(lg, tg, 2 * u + 1, lg2, lt, r2acc);
    }

    // Remaining rows (leftover full group if ngroups odd, plus any sub-4
    // tail group). Group boundaries preserved: rest starts at a group start.
    // The 4*nhet*ssq formula is cnt-independent, so partial groups are fine.
    if (blockIdx.x == 0 && threadIdx.x == 0 && rest_rows > 0) {
        for (int base = 0; base < rest_rows; base += 4) {
            float ssq = 0.0f;
            int nhet = 0;
            int gend = min(base + 4, rest_rows);
            for (int r = base; r < gend; r++) {
                row(logits_rest[r * 3 + 0], logits_rest[r * 3 + 1],
                    logits_rest[r * 3 + 2], targets_rest[r],
                    lg2, lt, ssq, nhet);
            }
            r2acc = fmaf((float)(4 * nhet), ssq, r2acc);
        }
    }

    // Per-thread total: ce = ln2 * lg2 - lt ; r2_loss = -r2acc
    double local = (double)(0.69314718055994531f * lg2 - lt - r2acc);

    // Warp reduce (double)
    #pragma unroll
    for (int o = 16; o > 0; o >>= 1)
        local += __shfl_down_sync(0xffffffffu, local, o);

    __shared__ double ws[8];
    if ((threadIdx.x & 31) == 0) ws[threadIdx.x >> 5] = local;
    __syncthreads();

    if (threadIdx.x == 0) {
        double v = 0.0;
        #pragma unroll
        for (int w = 0; w < 8; w++) v += ws[w];

        atomicAdd(&g_acc, v);
        __threadfence();
        unsigned int ticket = atomicAdd(&g_done, 1u);
        if (ticket == gridDim.x - 1) {
            double total = atomicAdd(&g_acc, 0.0);   // coherent read of full sum
            out[0] = (float)total;
            g_acc  = 0.0;                            // self-reset for next replay
            __threadfence();
            g_done = 0u;
        }
    }
}

extern "C" void kernel_launch(void* const* d_in, const int* in_sizes, int n_in,
                              void* d_out, int out_size) {
    const float* logits  = (const float*)d_in[0];   // (N, 3) fp32
    const int*   targets = (const int*)d_in[1];     // (N,)  int32
    float* out = (float*)d_out;

    const int n       = in_sizes[1];                // number of rows
    const int ngroups = n / 4;
    const int nunits  = ngroups / 2;                // 8 rows per unit
    const int rest    = n - nunits * 8;             // leftover rows

    const int threads = 256;
    const int blocks  = 1184;

    imputation_loss_kernel<<<blocks, threads>>>(
        (const float4*)logits, (const int4*)targets, nunits,
        logits + (long long)nunits * 24, targets + (long long)nunits * 8,
        rest, out);
}

// round 7
// speedup vs baseline: 1.1831x; 1.1831x over previous
#include <cuda_runtime.h>

// Scalar accumulator + completion counter (device globals; self-resetting so
// the kernel is deterministic across CUDA-graph replays).
__device__ double       g_acc  = 0.0;
__device__ unsigned int g_done = 0u;

// Per-row work, all fp32. Accumulates:
//   lg2  += log2(sum exp(l))          (CE log-sum-exp part, ln2 folded later)
//   lt   += l[target]                 (CE picked-logit part)
//   ssq  += (0.5 - p0)^2              (r2 squared deviation)
//   nhet += (target == 1)
// No max-subtraction: logits ~ N(0,1) (|l| < ~6), exp cannot overflow.
__device__ __forceinline__ void row(float l0, float l1, float l2, int t,
                                    float& lg2, float& lt,
                                    float& ssq, int& nhet) {
    float e0 = __expf(l0);
    float e1 = __expf(l1);
    float e2 = __expf(l2);
    float s  = e0 + e1 + e2;
    lg2 += __log2f(s);
    float p0 = __fdividef(e0, s);
    float d  = 0.5f - p0;
    ssq  = fmaf(d, d, ssq);
    lt  += (t == 1) ? l1 : ((t == 2) ? l2 : l0);
    nhet += (t == 1) ? 1 : 0;
}

__global__ void __launch_bounds__(256)
imputation_loss_kernel(const float4* __restrict__ lg,
                       const int4*  __restrict__ tg,
                       int ngroups,
                       const float* __restrict__ logits_tail,
                       const int*   __restrict__ targets_tail,
                       int tail_rows,
                       float* __restrict__ out) {
    float lg2 = 0.0f, lt = 0.0f, r2acc = 0.0f;

    const int stride = gridDim.x * blockDim.x;
    for (int g = blockIdx.x * blockDim.x + threadIdx.x; g < ngroups; g += stride) {
        // One group: 4 rows x 3 logits = 3 float4 (contiguous 48B per thread)
        float4 a = lg[g * 3 + 0];
        float4 b = lg[g * 3 + 1];
        float4 c = lg[g * 3 + 2];
        int4   t = tg[g];
        float ssq = 0.0f;
        int nhet = 0;
        row(a.x, a.y, a.z, t.x, lg2, lt, ssq, nhet);
        row(a.w, b.x, b.y, t.y, lg2, lt, ssq, nhet);
        row(b.z, b.w, c.x, t.z, lg2, lt, ssq, nhet);
        row(c.y, c.z, c.w, t.w, lg2, lt, ssq, nhet);
        // Group r2 contribution: cnt cancels out of the reference formula,
        // leaving exactly 4 * nhet * ssq (subtracted at the end).
        r2acc = fmaf((float)(4 * nhet), ssq, r2acc);
    }

    // Sub-4 tail group (rows beyond ngroups*4); formula is cnt-independent.
    if (blockIdx.x == 0 && threadIdx.x == 0 && tail_rows > 0) {
        float ssq = 0.0f;
        int nhet = 0;
        for (int r = 0; r < tail_rows; r++) {
            row(logits_tail[r * 3 + 0], logits_tail[r * 3 + 1],
                logits_tail[r * 3 + 2], targets_tail[r],
                lg2, lt, ssq, nhet);
        }
        r2acc = fmaf((float)(4 * nhet), ssq, r2acc);
    }

    // Per-thread total: ce = ln2 * lg2 - lt ; r2_loss = -r2acc
    double local = (double)(0.69314718055994531f * lg2 - lt - r2acc);

    // Warp reduce (double)
    #pragma unroll
    for (int o = 16; o > 0; o >>= 1)
        local += __shfl_down_sync(0xffffffffu, local, o);

    __shared__ double ws[8];
    if ((threadIdx.x & 31) == 0) ws[threadIdx.x >> 5] = local;
    __syncthreads();

    if (threadIdx.x == 0) {
        double v = 0.0;
        #pragma unroll
        for (int w = 0; w < 8; w++) v += ws[w];

        atomicAdd(&g_acc, v);
        __threadfence();
        unsigned int ticket = atomicAdd(&g_done, 1u);
        if (ticket == gridDim.x - 1) {
            double total = atomicAdd(&g_acc, 0.0);   // coherent read of full sum
            out[0] = (float)total;
            g_acc  = 0.0;                            // self-reset for next replay
            __threadfence();
            g_done = 0u;
        }
    }
}

extern "C" void kernel_launch(void* const* d_in, const int* in_sizes, int n_in,
                              void* d_out, int out_size) {
    const float* logits  = (const float*)d_in[0];   // (N, 3) fp32
    const int*   targets = (const int*)d_in[1];     // (N,)  int32
    float* out = (float*)d_out;

    const int n       = in_sizes[1];                // number of rows
    const int ngroups = n / 4;
    const int tail    = n - ngroups * 4;

    // 1024 blocks x 256 = 262144 threads. For N = 8388608 (ngroups = 2^21)
    // every thread runs exactly 8 iterations — perfect balance — and all
    // 1024 CTAs are resident in a single wave (8 CTAs/SM x 148 SMs = 1184).
    const int threads = 256;
    const int blocks  = 1024;

    imputation_loss_kernel<<<blocks, threads>>>(
        (const float4*)logits, (const int4*)targets, ngroups,
        logits + (long long)ngroups * 12, targets + (long long)ngroups * 4,
        tail, out);
}